// round 14
// baseline (speedup 1.0000x reference)
#include <cuda_runtime.h>
#include <cuda_fp16.h>
#include <math.h>
#include <stdint.h>

// Problem constants (fixed shapes)
#define BB 4
#define TT 4096
#define DD 1024
#define SPAN 128
#define NB (TT / SPAN)      // 32
#define MROWS (BB * TT)     // 16384

// Scratch (device globals: no allocation APIs allowed)
__device__ __half g_xh[(size_t)MROWS * DD];    // fp16 x
__device__ __half g_wh[(size_t)3 * DD * DD];   // fp16 Wq/Wk/Wv
__device__ __half g_q[(size_t)MROWS * DD];     // q fp16 row-major
__device__ __half g_k[(size_t)MROWS * DD];     // k fp16 row-major
__device__ __half g_v[(size_t)MROWS * DD];     // v fp16 row-major

__device__ __forceinline__ uint32_t smem_u32(const void* p) {
    uint32_t a;
    asm("{ .reg .u64 t; cvta.to.shared.u64 t, %1; cvt.u32.u64 %0, t; }"
        : "=r"(a) : "l"(p));
    return a;
}

#define LDMATRIX_X4(r0, r1, r2, r3, addr) \
    asm volatile("ldmatrix.sync.aligned.m8n8.x4.shared.b16 {%0,%1,%2,%3}, [%4];" \
                 : "=r"(r0), "=r"(r1), "=r"(r2), "=r"(r3) : "r"(addr))
#define LDMATRIX_X4T(r0, r1, r2, r3, addr) \
    asm volatile("ldmatrix.sync.aligned.m8n8.x4.trans.shared.b16 {%0,%1,%2,%3}, [%4];" \
                 : "=r"(r0), "=r"(r1), "=r"(r2), "=r"(r3) : "r"(addr))
#define MMA_F16(c0, c1, c2, c3, a0, a1, a2, a3, b0, b1) \
    asm volatile("mma.sync.aligned.m16n8k16.row.col.f32.f16.f16.f32 " \
                 "{%0,%1,%2,%3}, {%4,%5,%6,%7}, {%8,%9}, {%0,%1,%2,%3};" \
                 : "+f"(c0), "+f"(c1), "+f"(c2), "+f"(c3) \
                 : "r"(a0), "r"(a1), "r"(a2), "r"(a3), "r"(b0), "r"(b1))
#define CP_ASYNC_16(dst, src) \
    asm volatile("cp.async.cg.shared.global [%0], [%1], 16;" \
                 :: "r"(dst), "l"(src) : "memory")
#define CP_ASYNC_COMMIT() asm volatile("cp.async.commit_group;" ::: "memory")
#define CP_ASYNC_WAIT(n)  asm volatile("cp.async.wait_group %0;" :: "n"(n) : "memory")

// ---------------------------------------------------------------------------
// Convert fp32 -> fp16
// ---------------------------------------------------------------------------
__global__ __launch_bounds__(256) void cvt_f16(const float* __restrict__ src,
                                               __half* __restrict__ dst,
                                               int n4) {
    int i = blockIdx.x * 256 + threadIdx.x;
    if (i >= n4) return;
    float4 v = reinterpret_cast<const float4*>(src)[i];
    ushort4 o;
    o.x = __half_as_ushort(__float2half_rn(v.x));
    o.y = __half_as_ushort(__float2half_rn(v.y));
    o.z = __half_as_ushort(__float2half_rn(v.z));
    o.w = __half_as_ushort(__float2half_rn(v.w));
    reinterpret_cast<ushort4*>(dst)[i] = o;
}

// Fused conversion of the 3 weight matrices in one launch
__global__ __launch_bounds__(256) void cvt_f16_w3(const float* __restrict__ w0,
                                                  const float* __restrict__ w1,
                                                  const float* __restrict__ w2,
                                                  __half* __restrict__ dst) {
    const int w4 = DD * DD / 4;                  // 262144 float4 per matrix
    int i = blockIdx.x * 256 + threadIdx.x;      // 0 .. 3*w4-1
    if (i >= 3 * w4) return;
    const float* src = (i < w4) ? w0 : (i < 2 * w4) ? w1 : w2;
    int j = (i < w4) ? i : (i < 2 * w4) ? i - w4 : i - 2 * w4;
    float4 v = reinterpret_cast<const float4*>(src)[j];
    ushort4 o;
    o.x = __half_as_ushort(__float2half_rn(v.x));
    o.y = __half_as_ushort(__float2half_rn(v.y));
    o.z = __half_as_ushort(__float2half_rn(v.z));
    o.w = __half_as_ushort(__float2half_rn(v.w));
    reinterpret_cast<ushort4*>(dst)[i] = o;
}

// ---------------------------------------------------------------------------
// fp16 single-pass tensor-core GEMM:  out = x @ W^T + bias  (fp16 out)
// CTA tile M=128 x N=128, K-chunk 64 fp16 (128B rows), 2-stage cp.async.
// 256 threads = 8 warps (2 m x 4 n), warp tile 64x32, mma m16n8k16 f16.
// ---------------------------------------------------------------------------
struct GemmArgs {
    const __half* xh;
    const __half* wh[3];
    const float* bias[3];
    __half* out[3];
};

#define GC_CHUNKS (DD / 64)        // 16 K-chunks of 64 fp16
#define GT_TILE 16384u             // 128 rows x 128B
#define GT_STAGE 32768u            // A tile + B tile
#define GEMM_DSMEM (2u * GT_STAGE) // 64 KB

__global__ __launch_bounds__(256, 2) void qkv_tc_gemm(GemmArgs args) {
    extern __shared__ char dsm[];
    const int tid = threadIdx.x;
    const int wid = tid >> 5;
    const int lane = tid & 31;
    const int bn = blockIdx.x * 128;
    const int bm = blockIdx.y * 128;
    const int z  = blockIdx.z;
    const int warp_m = wid >> 2;
    const int warp_n = wid & 3;

    const uint32_t smem_base = smem_u32(dsm);

    const __half* At = args.xh    + (size_t)bm * DD;
    const __half* Bt = args.wh[z] + (size_t)bn * DD;

    auto load_stage = [&](int c, int buf) {
        const int k0 = c * 64;
        const uint32_t sb = smem_base + buf * GT_STAGE;
#pragma unroll
        for (int i = 0; i < 4; ++i) {
            int idx = tid + i * 256;
            int r = idx >> 3, ch = idx & 7;
            uint32_t dst = (uint32_t)(r * 128 + ((ch ^ (r & 7)) * 16));
            const size_t go = (size_t)r * DD + k0 + ch * 8;
            CP_ASYNC_16(sb + dst, At + go);
            CP_ASYNC_16(sb + GT_TILE + dst, Bt + go);
        }
        CP_ASYNC_COMMIT();
    };

    float acc[4][4][4];
#pragma unroll
    for (int mt = 0; mt < 4; ++mt)
#pragma unroll
        for (int nt = 0; nt < 4; ++nt)
#pragma unroll
            for (int j = 0; j < 4; ++j) acc[mt][nt][j] = 0.0f;

    const int a_row = warp_m * 64 + (lane & 15);
    const uint32_t a_sw = (uint32_t)((a_row & 7) * 16);
    const uint32_t a_kb = (uint32_t)((lane >> 4) * 16);
    const int b_row = warp_n * 32 + (lane & 7) + ((lane >> 4) << 3);
    const uint32_t b_sw = (uint32_t)((lane & 7) * 16);
    const uint32_t b_kb = (uint32_t)(((lane >> 3) & 1) * 16);

    load_stage(0, 0);

    for (int c = 0; c < GC_CHUNKS; ++c) {
        const int buf = c & 1;
        if (c + 1 < GC_CHUNKS) {
            load_stage(c + 1, buf ^ 1);
            CP_ASYNC_WAIT(1);
        } else {
            CP_ASYNC_WAIT(0);
        }
        __syncthreads();

        const uint32_t sb = smem_base + buf * GT_STAGE;
        const uint32_t a_base = sb + a_row * 128;
        const uint32_t b_base = sb + GT_TILE;

#pragma unroll
        for (int ks = 0; ks < 4; ++ks) {
            const uint32_t akb = (uint32_t)(ks * 32) + a_kb;
            uint32_t a[4][4];
#pragma unroll
            for (int mt = 0; mt < 4; ++mt)
                LDMATRIX_X4(a[mt][0], a[mt][1], a[mt][2], a[mt][3],
                            a_base + (uint32_t)(mt * 16 * 128) + (akb ^ a_sw));
#pragma unroll
            for (int ntp = 0; ntp < 2; ++ntp) {
                const uint32_t ba = (uint32_t)((b_row + ntp * 16) * 128) +
                                    (((uint32_t)(ks * 32) + b_kb) ^ b_sw);
                uint32_t b0, b1, b2, b3;
                LDMATRIX_X4(b0, b1, b2, b3, b_base + ba);
                const int n0 = ntp * 2, n1 = ntp * 2 + 1;
#pragma unroll
                for (int mt = 0; mt < 4; ++mt) {
                    MMA_F16(acc[mt][n0][0], acc[mt][n0][1], acc[mt][n0][2], acc[mt][n0][3],
                            a[mt][0], a[mt][1], a[mt][2], a[mt][3], b0, b1);
                    MMA_F16(acc[mt][n1][0], acc[mt][n1][1], acc[mt][n1][2], acc[mt][n1][3],
                            a[mt][0], a[mt][1], a[mt][2], a[mt][3], b2, b3);
                }
            }
        }
        __syncthreads();
    }

    // Epilogue: add bias, fp16 store
    const float* bias = args.bias[z];
    __half* out = args.out[z];
    const int er = bm + warp_m * 64 + (lane >> 2);
    const int ec = bn + warp_n * 32 + (lane & 3) * 2;
#pragma unroll
    for (int mt = 0; mt < 4; ++mt) {
#pragma unroll
        for (int nt = 0; nt < 4; ++nt) {
            const int r0 = er + mt * 16;
            const int cc = ec + nt * 8;
            __half2 p0, p1;
            p0.x = __float2half_rn(acc[mt][nt][0] + bias[cc]);
            p0.y = __float2half_rn(acc[mt][nt][1] + bias[cc + 1]);
            p1.x = __float2half_rn(acc[mt][nt][2] + bias[cc]);
            p1.y = __float2half_rn(acc[mt][nt][3] + bias[cc + 1]);
            *reinterpret_cast<__half2*>(out + (size_t)r0 * DD + cc) = p0;
            *reinterpret_cast<__half2*>(out + (size_t)(r0 + 8) * DD + cc) = p1;
        }
    }
}

// ---------------------------------------------------------------------------
// fp16 single-pass windowed attention with fine-grained mma-tile skipping.
// One CTA per (b, n): 128 q x 256 keys. 8 warps (2 m x 4 n).
// ---------------------------------------------------------------------------
struct AttnArgs {
    const __half *q, *k, *v;
    float* out;
};

#define AC_CHUNKS (DD / 64)        // 16 d-chunks for phase 1
#define A_STAGE 49152u             // Q 16K | K 32K (fp16, 64 d per stage)
#define A_QO 0u
#define A_KO 16384u
#define P_OFF 0u                   // phase 3: P 64K (128 rows x 512B)
#define V_BASE 65536u              //          V stages: 2 x 16K
#define ATTN_DSMEM 98304u

__global__ __launch_bounds__(256) void attn_tc(AttnArgs a) {
    extern __shared__ char dsm[];
    __shared__ float redmax[128][4];
    __shared__ float redsum[128][4];

    const int tid = threadIdx.x;
    const int wid = tid >> 5;
    const int lane = tid & 31;
    const int wm = wid >> 2;
    const int wn = wid & 3;
    const int nblk = blockIdx.x;
    const int b = blockIdx.y;
    const size_t qrow0 = (size_t)b * TT + (size_t)nblk * SPAN;
    const int kv0 = (nblk - 1) * SPAN;
    const uint32_t smem = smem_u32(dsm);

    // Per-(mt,ntp) 16x16 sub-tile mask: needed iff some (row,col) satisfies
    // col > row && col <= row+128 && (nblk>0 || col>=128).
    // rows: wm*64+mt*16 .. +15 ; cols: wn*64+ntp*16 .. +15
    bool tile_on[4][4];
    bool any_on = false;
    bool ntp_on[4];
#pragma unroll
    for (int ntp = 0; ntp < 4; ++ntp) ntp_on[ntp] = false;
#pragma unroll
    for (int mt = 0; mt < 4; ++mt) {
#pragma unroll
        for (int ntp = 0; ntp < 4; ++ntp) {
            const int rmin = wm * 64 + mt * 16;
            const int rmax = rmin + 15;
            const int cmin = wn * 64 + ntp * 16;
            const int cmax = cmin + 15;
            bool on = (cmax > rmin) && (cmin <= rmax + SPAN) &&
                      (nblk > 0 || cmax >= SPAN);
            tile_on[mt][ntp] = on;
            any_on |= on;
            ntp_on[ntp] |= on;
        }
    }

    // ---------------- Phase 1: S = Q @ K^T (fp16) ----------------
    float acc[4][8][4];
#pragma unroll
    for (int mt = 0; mt < 4; ++mt)
#pragma unroll
        for (int nt = 0; nt < 8; ++nt)
#pragma unroll
            for (int j = 0; j < 4; ++j) acc[mt][nt][j] = 0.0f;

    auto load_stage1 = [&](int c, int buf) {
        const int k0 = c * 64;
        const uint32_t sb = smem + buf * A_STAGE;
#pragma unroll
        for (int i = 0; i < 4; ++i) {
            int idx = tid + i * 256;
            int r = idx >> 3, ch = idx & 7;
            uint32_t dst = (uint32_t)(r * 128 + ((ch ^ (r & 7)) * 16));
            CP_ASYNC_16(sb + A_QO + dst, a.q + (qrow0 + r) * DD + k0 + ch * 8);
        }
#pragma unroll
        for (int i = 0; i < 8; ++i) {
            int idx = tid + i * 256;
            int r = idx >> 3, ch = idx & 7;
            int krow = kv0 + r; if (krow < 0) krow = 0;
            uint32_t dst = (uint32_t)(r * 128 + ((ch ^ (r & 7)) * 16));
            CP_ASYNC_16(sb + A_KO + dst, a.k + ((size_t)b * TT + krow) * DD + k0 + ch * 8);
        }
        CP_ASYNC_COMMIT();
    };

    const int a_row = wm * 64 + (lane & 15);
    const uint32_t a_sw = (uint32_t)((a_row & 7) * 16);
    const uint32_t a_kb = (uint32_t)((lane >> 4) * 16);
    const int b_rowc = (lane & 7) + ((lane >> 4) << 3);
    const uint32_t b_sw = (uint32_t)((lane & 7) * 16);
    const uint32_t b_kb = (uint32_t)(((lane >> 3) & 1) * 16);

    load_stage1(0, 0);

    for (int c = 0; c < AC_CHUNKS; ++c) {
        const int buf = c & 1;
        if (c + 1 < AC_CHUNKS) {
            load_stage1(c + 1, (c + 1) & 1);
            CP_ASYNC_WAIT(1);
        } else {
            CP_ASYNC_WAIT(0);
        }
        __syncthreads();

        if (any_on) {
            const uint32_t sb = smem + buf * A_STAGE;
            const uint32_t a_base = sb + A_QO + a_row * 128;
            const uint32_t b_base = sb + A_KO;

#pragma unroll
            for (int ks = 0; ks < 4; ++ks) {
                const uint32_t akb = (uint32_t)(ks * 32) + a_kb;
                uint32_t af[4][4];
#pragma unroll
                for (int mt = 0; mt < 4; ++mt)
                    LDMATRIX_X4(af[mt][0], af[mt][1], af[mt][2], af[mt][3],
                                a_base + (uint32_t)(mt * 16 * 128) + (akb ^ a_sw));
#pragma unroll
                for (int ntp = 0; ntp < 4; ++ntp) {
                    if (!ntp_on[ntp]) continue;
                    const int brow = wn * 64 + ntp * 16 + b_rowc;
                    const uint32_t ba = (uint32_t)(brow * 128) +
                                        (((uint32_t)(ks * 32) + b_kb) ^ b_sw);
                    uint32_t b0, b1, b2, b3;
                    LDMATRIX_X4(b0, b1, b2, b3, b_base + ba);
                    const int n0 = ntp * 2, n1 = ntp * 2 + 1;
#pragma unroll
                    for (int mt = 0; mt < 4; ++mt) {
                        if (!tile_on[mt][ntp]) continue;
                        MMA_F16(acc[mt][n0][0], acc[mt][n0][1], acc[mt][n0][2], acc[mt][n0][3],
                                af[mt][0], af[mt][1], af[mt][2], af[mt][3], b0, b1);
                        MMA_F16(acc[mt][n1][0], acc[mt][n1][1], acc[mt][n1][2], acc[mt][n1][3],
                                af[mt][0], af[mt][1], af[mt][2], af[mt][3], b2, b3);
                    }
                }
            }
        }
        __syncthreads();
    }

    // ---------------- Phase 2: register softmax ----------------
    const float scale = 0.03125f;   // 1/sqrt(1024)
#pragma unroll
    for (int mt = 0; mt < 4; ++mt) {
#pragma unroll
        for (int half = 0; half < 2; ++half) {
            const int row = wm * 64 + mt * 16 + half * 8 + (lane >> 2);
            float m = -1e30f;
#pragma unroll
            for (int nt = 0; nt < 8; ++nt) {
#pragma unroll
                for (int j = 0; j < 2; ++j) {
                    const int col = wn * 64 + nt * 8 + (lane & 3) * 2 + j;
                    const bool ok = (col > row) && (col <= row + SPAN) &&
                                    (nblk > 0 || col >= SPAN);
                    float s = ok ? acc[mt][nt][half * 2 + j] * scale : -1e30f;
                    acc[mt][nt][half * 2 + j] = s;
                    m = fmaxf(m, s);
                }
            }
            m = fmaxf(m, __shfl_xor_sync(0xFFFFFFFFu, m, 1));
            m = fmaxf(m, __shfl_xor_sync(0xFFFFFFFFu, m, 2));
            if ((lane & 3) == 0) redmax[row][wn] = m;
        }
    }
    __syncthreads();
#pragma unroll
    for (int mt = 0; mt < 4; ++mt) {
#pragma unroll
        for (int half = 0; half < 2; ++half) {
            const int row = wm * 64 + mt * 16 + half * 8 + (lane >> 2);
            float m = fmaxf(fmaxf(redmax[row][0], redmax[row][1]),
                            fmaxf(redmax[row][2], redmax[row][3]));
            float sum = 0.0f;
#pragma unroll
            for (int nt = 0; nt < 8; ++nt) {
#pragma unroll
                for (int j = 0; j < 2; ++j) {
                    float s = acc[mt][nt][half * 2 + j];
                    float p = (s > -1e29f) ? __expf(s - m) : 0.0f;
                    acc[mt][nt][half * 2 + j] = p;
                    sum += p;
                }
            }
            sum += __shfl_xor_sync(0xFFFFFFFFu, sum, 1);
            sum += __shfl_xor_sync(0xFFFFFFFFu, sum, 2);
            if ((lane & 3) == 0) redsum[row][wn] = sum;
        }
    }
    __syncthreads();
    // Write P (fp16) to smem: 128 rows x 512B, swizzled
#pragma unroll
    for (int mt = 0; mt < 4; ++mt) {
#pragma unroll
        for (int half = 0; half < 2; ++half) {
            const int row = wm * 64 + mt * 16 + half * 8 + (lane >> 2);
            const float inv = 1.0f / (redsum[row][0] + redsum[row][1] +
                                      redsum[row][2] + redsum[row][3]);
#pragma unroll
            for (int nt = 0; nt < 8; ++nt) {
                const int col = wn * 64 + nt * 8 + (lane & 3) * 2;
                __half2 h;
                h.x = __float2half_rn(acc[mt][nt][half * 2 + 0] * inv);
                h.y = __float2half_rn(acc[mt][nt][half * 2 + 1] * inv);
                uint32_t off = (uint32_t)(row * 512 + col * 2);
                off ^= (off >> 5) & 0x70;
                asm volatile("st.shared.b32 [%0], %1;"
                             :: "r"(smem + P_OFF + off), "r"(*(uint32_t*)&h) : "memory");
            }
        }
    }
    __syncthreads();

    // ---------------- Phase 3: O = P @ V (fp16 single) ----------------
    auto load_v = [&](int kc, int buf, int d0) {
        if (nblk == 0 && kc < 4) return;   // all-zero P for every warp: skip load
        const uint32_t sb = smem + V_BASE + buf * 16384u;
#pragma unroll
        for (int i = 0; i < 4; ++i) {
            int idx = tid + i * 256;
            int r = idx >> 5, ch = idx & 31;
            int vrow = kv0 + kc * 32 + r; if (vrow < 0) vrow = 0;
            uint32_t dst = (uint32_t)(r * 512 + ((ch ^ (r & 7)) * 16));
            CP_ASYNC_16(sb + dst, a.v + ((size_t)b * TT + vrow) * DD + d0 + ch * 8);
        }
    };

    for (int dc = 0; dc < 4; ++dc) {
        const int d0 = dc * 256;
        float acc2[4][8][4];
#pragma unroll
        for (int mt = 0; mt < 4; ++mt)
#pragma unroll
            for (int nt = 0; nt < 8; ++nt)
#pragma unroll
                for (int j = 0; j < 4; ++j) acc2[mt][nt][j] = 0.0f;

        load_v(0, 0, d0);
        CP_ASYNC_COMMIT();
        for (int kc = 0; kc < 8; ++kc) {
            const int buf = kc & 1;
            if (kc + 1 < 8) {
                load_v(kc + 1, (kc + 1) & 1, d0);
                CP_ASYNC_COMMIT();
                CP_ASYNC_WAIT(1);
            } else {
                CP_ASYNC_WAIT(0);
            }
            __syncthreads();

            const bool pskip = ((kc * 32 + 31) <= (wm * 64)) ||
                               ((kc * 32) > (wm * 64 + 191)) ||
                               (nblk == 0 && kc < 4);
            if (!pskip) {
                const uint32_t vb = smem + V_BASE + buf * 16384u;
#pragma unroll
                for (int ks = 0; ks < 2; ++ks) {
                    const int kbase = kc * 32 + ks * 16;
                    uint32_t pf[4][4];
#pragma unroll
                    for (int mt = 0; mt < 4; ++mt) {
                        const int prow = wm * 64 + mt * 16 + (lane & 15);
                        uint32_t aoff = (uint32_t)(prow * 512 + kbase * 2 + (lane >> 4) * 16);
                        aoff ^= (aoff >> 5) & 0x70;
                        LDMATRIX_X4(pf[mt][0], pf[mt][1], pf[mt][2], pf[mt][3],
                                    smem + P_OFF + aoff);
                    }
#pragma unroll
                    for (int ntp = 0; ntp < 4; ++ntp) {
                        const int vrow = ks * 16 + (lane & 15);
                        const int vcol = wn * 64 + ntp * 16 + ((lane >> 4) << 3);
                        uint32_t boff = (uint32_t)(vrow * 512 + vcol * 2);
                        boff ^= (boff >> 5) & 0x70;
                        uint32_t v0, v1, v2, v3;
                        LDMATRIX_X4T(v0, v1, v2, v3, vb + boff);
                        const int n0 = ntp * 2, n1 = ntp * 2 + 1;
#pragma unroll
                        for (int mt = 0; mt < 4; ++mt) {
                            MMA_F16(acc2[mt][n0][0], acc2[mt][n0][1], acc2[mt][n0][2], acc2[mt][n0][3],
                                    pf[mt][0], pf[mt][1], pf[mt][2], pf[mt][3], v0, v1);
                            MMA_F16(acc2[mt][n1][0], acc2[mt][n1][1], acc2[mt][n1][2], acc2[mt][n1][3],
                                    pf[mt][0], pf[mt][1], pf[mt][2], pf[mt][3], v2, v3);
                        }
                    }
                }
            }
            __syncthreads();
        }

        // Epilogue for this d-chunk
#pragma unroll
        for (int mt = 0; mt < 4; ++mt) {
#pragma unroll
            for (int nt = 0; nt < 8; ++nt) {
                const size_t row = qrow0 + wm * 64 + mt * 16 + (lane >> 2);
                const int col = d0 + wn * 64 + nt * 8 + (lane & 3) * 2;
                float2 v0 = make_float2(acc2[mt][nt][0], acc2[mt][nt][1]);
                float2 v1 = make_float2(acc2[mt][nt][2], acc2[mt][nt][3]);
                *reinterpret_cast<float2*>(a.out + row * DD + col) = v0;
                *reinterpret_cast<float2*>(a.out + (row + 8) * DD + col) = v1;
            }
        }
    }
}

// ---------------------------------------------------------------------------
extern "C" void kernel_launch(void* const* d_in, const int* in_sizes, int n_in,
                              void* d_out, int out_size) {
    const float* x  = (const float*)d_in[0];
    const float* Wq = (const float*)d_in[1];
    const float* bq = (const float*)d_in[2];
    const float* Wk = (const float*)d_in[3];
    const float* bk = (const float*)d_in[4];
    const float* Wv = (const float*)d_in[5];
    const float* bv = (const float*)d_in[6];
    float* out = (float*)d_out;

    __half *xh, *wh, *q, *k, *v;
    cudaGetSymbolAddress((void**)&xh, g_xh);
    cudaGetSymbolAddress((void**)&wh, g_wh);
    cudaGetSymbolAddress((void**)&q, g_q);
    cudaGetSymbolAddress((void**)&k, g_k);
    cudaGetSymbolAddress((void**)&v, g_v);

    // Convert fp32 -> fp16 (x in one launch, all 3 weights in one launch)
    {
        int n4 = MROWS * DD / 4;
        cvt_f16<<<(n4 + 255) / 256, 256>>>(x, xh, n4);
        int w4x3 = 3 * DD * DD / 4;
        cvt_f16_w3<<<(w4x3 + 255) / 256, 256>>>(Wq, Wk, Wv, wh);
    }

    GemmArgs ga;
    ga.xh = xh;
    ga.wh[0] = wh;
    ga.wh[1] = wh + 1 * (size_t)DD * DD;
    ga.wh[2] = wh + 2 * (size_t)DD * DD;
    ga.bias[0] = bq; ga.bias[1] = bk; ga.bias[2] = bv;
    ga.out[0] = q; ga.out[1] = k; ga.out[2] = v;

    cudaFuncSetAttribute(qkv_tc_gemm, cudaFuncAttributeMaxDynamicSharedMemorySize,
                         GEMM_DSMEM);
    qkv_tc_gemm<<<dim3(DD / 128, MROWS / 128, 3), 256, GEMM_DSMEM>>>(ga);

    AttnArgs aa;
    aa.q = q; aa.k = k; aa.v = v;
    aa.out = out;
    cudaFuncSetAttribute(attn_tc, cudaFuncAttributeMaxDynamicSharedMemorySize,
                         ATTN_DSMEM);
    attn_tc<<<dim3(NB, BB), 256, ATTN_DSMEM>>>(aa);
}

// round 17
// speedup vs baseline: 1.0648x; 1.0648x over previous
#include <cuda_runtime.h>
#include <cuda_fp16.h>
#include <math.h>
#include <stdint.h>

// Problem constants (fixed shapes)
#define BB 4
#define TT 4096
#define DD 1024
#define SPAN 128
#define NB2 (TT / 64)       // 64 query blocks of 64 rows per batch
#define MROWS (BB * TT)     // 16384

// Scratch (device globals: no allocation APIs allowed)
__device__ __half g_xh[(size_t)MROWS * DD];    // fp16 x
__device__ __half g_wh[(size_t)3 * DD * DD];   // fp16 Wq/Wk/Wv
__device__ __half g_q[(size_t)MROWS * DD];     // q fp16 row-major
__device__ __half g_k[(size_t)MROWS * DD];     // k fp16 row-major
__device__ __half g_v[(size_t)MROWS * DD];     // v fp16 row-major

__device__ __forceinline__ uint32_t smem_u32(const void* p) {
    uint32_t a;
    asm("{ .reg .u64 t; cvta.to.shared.u64 t, %1; cvt.u32.u64 %0, t; }"
        : "=r"(a) : "l"(p));
    return a;
}

#define LDMATRIX_X4(r0, r1, r2, r3, addr) \
    asm volatile("ldmatrix.sync.aligned.m8n8.x4.shared.b16 {%0,%1,%2,%3}, [%4];" \
                 : "=r"(r0), "=r"(r1), "=r"(r2), "=r"(r3) : "r"(addr))
#define LDMATRIX_X4T(r0, r1, r2, r3, addr) \
    asm volatile("ldmatrix.sync.aligned.m8n8.x4.trans.shared.b16 {%0,%1,%2,%3}, [%4];" \
                 : "=r"(r0), "=r"(r1), "=r"(r2), "=r"(r3) : "r"(addr))
#define MMA_F16(c0, c1, c2, c3, a0, a1, a2, a3, b0, b1) \
    asm volatile("mma.sync.aligned.m16n8k16.row.col.f32.f16.f16.f32 " \
                 "{%0,%1,%2,%3}, {%4,%5,%6,%7}, {%8,%9}, {%0,%1,%2,%3};" \
                 : "+f"(c0), "+f"(c1), "+f"(c2), "+f"(c3) \
                 : "r"(a0), "r"(a1), "r"(a2), "r"(a3), "r"(b0), "r"(b1))
#define CP_ASYNC_16(dst, src) \
    asm volatile("cp.async.cg.shared.global [%0], [%1], 16;" \
                 :: "r"(dst), "l"(src) : "memory")
#define CP_ASYNC_COMMIT() asm volatile("cp.async.commit_group;" ::: "memory")
#define CP_ASYNC_WAIT(n)  asm volatile("cp.async.wait_group %0;" :: "n"(n) : "memory")

// ---------------------------------------------------------------------------
// Convert fp32 -> fp16
// ---------------------------------------------------------------------------
__global__ __launch_bounds__(256) void cvt_f16(const float* __restrict__ src,
                                               __half* __restrict__ dst,
                                               int n4) {
    int i = blockIdx.x * 256 + threadIdx.x;
    if (i >= n4) return;
    float4 v = reinterpret_cast<const float4*>(src)[i];
    ushort4 o;
    o.x = __half_as_ushort(__float2half_rn(v.x));
    o.y = __half_as_ushort(__float2half_rn(v.y));
    o.z = __half_as_ushort(__float2half_rn(v.z));
    o.w = __half_as_ushort(__float2half_rn(v.w));
    reinterpret_cast<ushort4*>(dst)[i] = o;
}

__global__ __launch_bounds__(256) void cvt_f16_w3(const float* __restrict__ w0,
                                                  const float* __restrict__ w1,
                                                  const float* __restrict__ w2,
                                                  __half* __restrict__ dst) {
    const int w4 = DD * DD / 4;
    int i = blockIdx.x * 256 + threadIdx.x;
    if (i >= 3 * w4) return;
    const float* src = (i < w4) ? w0 : (i < 2 * w4) ? w1 : w2;
    int j = (i < w4) ? i : (i < 2 * w4) ? i - w4 : i - 2 * w4;
    float4 v = reinterpret_cast<const float4*>(src)[j];
    ushort4 o;
    o.x = __half_as_ushort(__float2half_rn(v.x));
    o.y = __half_as_ushort(__float2half_rn(v.y));
    o.z = __half_as_ushort(__float2half_rn(v.z));
    o.w = __half_as_ushort(__float2half_rn(v.w));
    reinterpret_cast<ushort4*>(dst)[i] = o;
}

// ---------------------------------------------------------------------------
// fp16 single-pass tensor-core GEMM (unchanged; at the fallback-pipe
// instruction floor):  out = x @ W^T + bias  (fp16 out)
// ---------------------------------------------------------------------------
struct GemmArgs {
    const __half* xh;
    const __half* wh[3];
    const float* bias[3];
    __half* out[3];
};

#define GC_CHUNKS (DD / 64)
#define GT_TILE 16384u
#define GT_STAGE 32768u
#define GEMM_DSMEM (2u * GT_STAGE)

__global__ __launch_bounds__(256, 2) void qkv_tc_gemm(GemmArgs args) {
    extern __shared__ char dsm[];
    const int tid = threadIdx.x;
    const int wid = tid >> 5;
    const int lane = tid & 31;
    const int bn = blockIdx.x * 128;
    const int bm = blockIdx.y * 128;
    const int z  = blockIdx.z;
    const int warp_m = wid >> 2;
    const int warp_n = wid & 3;

    const uint32_t smem_base = smem_u32(dsm);

    const __half* At = args.xh    + (size_t)bm * DD;
    const __half* Bt = args.wh[z] + (size_t)bn * DD;

    auto load_stage = [&](int c, int buf) {
        const int k0 = c * 64;
        const uint32_t sb = smem_base + buf * GT_STAGE;
#pragma unroll
        for (int i = 0; i < 4; ++i) {
            int idx = tid + i * 256;
            int r = idx >> 3, ch = idx & 7;
            uint32_t dst = (uint32_t)(r * 128 + ((ch ^ (r & 7)) * 16));
            const size_t go = (size_t)r * DD + k0 + ch * 8;
            CP_ASYNC_16(sb + dst, At + go);
            CP_ASYNC_16(sb + GT_TILE + dst, Bt + go);
        }
        CP_ASYNC_COMMIT();
    };

    float acc[4][4][4];
#pragma unroll
    for (int mt = 0; mt < 4; ++mt)
#pragma unroll
        for (int nt = 0; nt < 4; ++nt)
#pragma unroll
            for (int j = 0; j < 4; ++j) acc[mt][nt][j] = 0.0f;

    const int a_row = warp_m * 64 + (lane & 15);
    const uint32_t a_sw = (uint32_t)((a_row & 7) * 16);
    const uint32_t a_kb = (uint32_t)((lane >> 4) * 16);
    const int b_row = warp_n * 32 + (lane & 7) + ((lane >> 4) << 3);
    const uint32_t b_sw = (uint32_t)((lane & 7) * 16);
    const uint32_t b_kb = (uint32_t)(((lane >> 3) & 1) * 16);

    load_stage(0, 0);

    for (int c = 0; c < GC_CHUNKS; ++c) {
        const int buf = c & 1;
        if (c + 1 < GC_CHUNKS) {
            load_stage(c + 1, buf ^ 1);
            CP_ASYNC_WAIT(1);
        } else {
            CP_ASYNC_WAIT(0);
        }
        __syncthreads();

        const uint32_t sb = smem_base + buf * GT_STAGE;
        const uint32_t a_base = sb + a_row * 128;
        const uint32_t b_base = sb + GT_TILE;

#pragma unroll
        for (int ks = 0; ks < 4; ++ks) {
            const uint32_t akb = (uint32_t)(ks * 32) + a_kb;
            uint32_t a[4][4];
#pragma unroll
            for (int mt = 0; mt < 4; ++mt)
                LDMATRIX_X4(a[mt][0], a[mt][1], a[mt][2], a[mt][3],
                            a_base + (uint32_t)(mt * 16 * 128) + (akb ^ a_sw));
#pragma unroll
            for (int ntp = 0; ntp < 2; ++ntp) {
                const uint32_t ba = (uint32_t)((b_row + ntp * 16) * 128) +
                                    (((uint32_t)(ks * 32) + b_kb) ^ b_sw);
                uint32_t b0, b1, b2, b3;
                LDMATRIX_X4(b0, b1, b2, b3, b_base + ba);
                const int n0 = ntp * 2, n1 = ntp * 2 + 1;
#pragma unroll
                for (int mt = 0; mt < 4; ++mt) {
                    MMA_F16(acc[mt][n0][0], acc[mt][n0][1], acc[mt][n0][2], acc[mt][n0][3],
                            a[mt][0], a[mt][1], a[mt][2], a[mt][3], b0, b1);
                    MMA_F16(acc[mt][n1][0], acc[mt][n1][1], acc[mt][n1][2], acc[mt][n1][3],
                            a[mt][0], a[mt][1], a[mt][2], a[mt][3], b2, b3);
                }
            }
        }
        __syncthreads();
    }

    const float* bias = args.bias[z];
    __half* out = args.out[z];
    const int er = bm + warp_m * 64 + (lane >> 2);
    const int ec = bn + warp_n * 32 + (lane & 3) * 2;
#pragma unroll
    for (int mt = 0; mt < 4; ++mt) {
#pragma unroll
        for (int nt = 0; nt < 4; ++nt) {
            const int r0 = er + mt * 16;
            const int cc = ec + nt * 8;
            __half2 p0, p1;
            p0.x = __float2half_rn(acc[mt][nt][0] + bias[cc]);
            p0.y = __float2half_rn(acc[mt][nt][1] + bias[cc + 1]);
            p1.x = __float2half_rn(acc[mt][nt][2] + bias[cc]);
            p1.y = __float2half_rn(acc[mt][nt][3] + bias[cc + 1]);
            *reinterpret_cast<__half2*>(out + (size_t)r0 * DD + cc) = p0;
            *reinterpret_cast<__half2*>(out + (size_t)(r0 + 8) * DD + cc) = p1;
        }
    }
}

// ---------------------------------------------------------------------------
// fp16 windowed attention, 64-row query blocks for occupancy.
// One CTA per (b, nblk2): 64 q rows x 192-key window (kb0 = nblk2*64 - 128).
// Valid: col > row && col <= row+128 && kb0+col >= 0  (key = kb0 + col).
// 256 threads = 8 warps: phase 1 warp tile 32q x 48k (2mt x 3ntp);
// phase 3 warp tile 32q x 64d. Smem 64 KB -> 2 CTAs/SM.
// ---------------------------------------------------------------------------
struct AttnArgs {
    const __half *q, *k, *v;
    float* out;
};

#define AC_CHUNKS (DD / 64)        // 16 d-chunks for phase 1
#define A_QO 0u                    // Q: 64 x 128B = 8 KB
#define A_KO 8192u                 // K: 192 x 128B = 24 KB
#define A_STAGE 32768u             // 2 stages -> 64 KB
#define P_OFF 0u                   // phase 3: P 64 rows x 512B = 32 KB
#define V_BASE 32768u              // V stages: 2 x 16 KB
#define ATTN_DSMEM 65536u

__global__ __launch_bounds__(256, 2) void attn_tc(AttnArgs a) {
    extern __shared__ char dsm[];
    __shared__ float redmax[64][4];
    __shared__ float redsum[64][4];

    const int tid = threadIdx.x;
    const int wid = tid >> 5;
    const int lane = tid & 31;
    const int wm = wid >> 2;        // 0..1 -> q rows 32*wm
    const int wn = wid & 3;         // 0..3
    const int nblk2 = blockIdx.x;   // 0..63
    const int b = blockIdx.y;
    const size_t qrow0 = (size_t)b * TT + (size_t)nblk2 * 64;
    const int kb0 = nblk2 * 64 - 128;   // first key (may be negative = padding)
    const uint32_t smem = smem_u32(dsm);

    // Per-(mt,ntp) 16x16 sub-tile mask (phase 1: 2mt x 3ntp)
    bool tile_on[2][3];
    bool ntp_on[3];
    bool any_on = false;
#pragma unroll
    for (int ntp = 0; ntp < 3; ++ntp) ntp_on[ntp] = false;
#pragma unroll
    for (int mt = 0; mt < 2; ++mt) {
#pragma unroll
        for (int ntp = 0; ntp < 3; ++ntp) {
            const int rmin = wm * 32 + mt * 16;
            const int rmax = rmin + 15;
            const int cmin = wn * 48 + ntp * 16;
            const int cmax = cmin + 15;
            bool on = (cmax > rmin) && (cmin <= rmax + SPAN) && (kb0 + cmax >= 0);
            tile_on[mt][ntp] = on;
            ntp_on[ntp] |= on;
            any_on |= on;
        }
    }

    // ---------------- Phase 1: S = Q @ K^T (fp16) ----------------
    float acc[2][6][4];
#pragma unroll
    for (int mt = 0; mt < 2; ++mt)
#pragma unroll
        for (int nt = 0; nt < 6; ++nt)
#pragma unroll
            for (int j = 0; j < 4; ++j) acc[mt][nt][j] = 0.0f;

    auto load_stage1 = [&](int c, int buf) {
        const int k0 = c * 64;
        const uint32_t sb = smem + buf * A_STAGE;
        // Q: 64 rows x 8 chunks = 512 -> 2/thread
#pragma unroll
        for (int i = 0; i < 2; ++i) {
            int idx = tid + i * 256;
            int r = idx >> 3, ch = idx & 7;
            uint32_t dst = (uint32_t)(r * 128 + ((ch ^ (r & 7)) * 16));
            CP_ASYNC_16(sb + A_QO + dst, a.q + (qrow0 + r) * DD + k0 + ch * 8);
        }
        // K: 192 rows x 8 chunks = 1536 -> 6/thread
#pragma unroll
        for (int i = 0; i < 6; ++i) {
            int idx = tid + i * 256;
            int r = idx >> 3, ch = idx & 7;
            int krow = kb0 + r; if (krow < 0) krow = 0;
            uint32_t dst = (uint32_t)(r * 128 + ((ch ^ (r & 7)) * 16));
            CP_ASYNC_16(sb + A_KO + dst, a.k + ((size_t)b * TT + krow) * DD + k0 + ch * 8);
        }
        CP_ASYNC_COMMIT();
    };

    const int a_row = wm * 32 + (lane & 15);
    const uint32_t a_sw = (uint32_t)((a_row & 7) * 16);
    const uint32_t a_kb = (uint32_t)((lane >> 4) * 16);
    const int b_rowc = (lane & 7) + ((lane >> 4) << 3);
    const uint32_t b_sw = (uint32_t)((lane & 7) * 16);
    const uint32_t b_kb = (uint32_t)(((lane >> 3) & 1) * 16);

    load_stage1(0, 0);

    for (int c = 0; c < AC_CHUNKS; ++c) {
        const int buf = c & 1;
        if (c + 1 < AC_CHUNKS) {
            load_stage1(c + 1, (c + 1) & 1);
            CP_ASYNC_WAIT(1);
        } else {
            CP_ASYNC_WAIT(0);
        }
        __syncthreads();

        if (any_on) {
            const uint32_t sb = smem + buf * A_STAGE;
            const uint32_t a_base = sb + A_QO + a_row * 128;
            const uint32_t b_base = sb + A_KO;

#pragma unroll
            for (int ks = 0; ks < 4; ++ks) {
                const uint32_t akb = (uint32_t)(ks * 32) + a_kb;
                uint32_t af[2][4];
#pragma unroll
                for (int mt = 0; mt < 2; ++mt)
                    LDMATRIX_X4(af[mt][0], af[mt][1], af[mt][2], af[mt][3],
                                a_base + (uint32_t)(mt * 16 * 128) + (akb ^ a_sw));
#pragma unroll
                for (int ntp = 0; ntp < 3; ++ntp) {
                    if (!ntp_on[ntp]) continue;
                    const int brow = wn * 48 + ntp * 16 + b_rowc;
                    const uint32_t ba = (uint32_t)(brow * 128) +
                                        (((uint32_t)(ks * 32) + b_kb) ^ b_sw);
                    uint32_t b0, b1, b2, b3;
                    LDMATRIX_X4(b0, b1, b2, b3, b_base + ba);
                    const int n0 = ntp * 2, n1 = ntp * 2 + 1;
#pragma unroll
                    for (int mt = 0; mt < 2; ++mt) {
                        if (!tile_on[mt][ntp]) continue;
                        MMA_F16(acc[mt][n0][0], acc[mt][n0][1], acc[mt][n0][2], acc[mt][n0][3],
                                af[mt][0], af[mt][1], af[mt][2], af[mt][3], b0, b1);
                        MMA_F16(acc[mt][n1][0], acc[mt][n1][1], acc[mt][n1][2], acc[mt][n1][3],
                                af[mt][0], af[mt][1], af[mt][2], af[mt][3], b2, b3);
                    }
                }
            }
        }
        __syncthreads();
    }

    // ---------------- Phase 2: register softmax ----------------
    const float scale = 0.03125f;   // 1/sqrt(1024)
#pragma unroll
    for (int mt = 0; mt < 2; ++mt) {
#pragma unroll
        for (int half = 0; half < 2; ++half) {
            const int row = wm * 32 + mt * 16 + half * 8 + (lane >> 2);
            float m = -1e30f;
#pragma unroll
            for (int nt = 0; nt < 6; ++nt) {
#pragma unroll
                for (int j = 0; j < 2; ++j) {
                    const int col = wn * 48 + nt * 8 + (lane & 3) * 2 + j;
                    const bool ok = (col > row) && (col <= row + SPAN) &&
                                    (kb0 + col >= 0);
                    float s = ok ? acc[mt][nt][half * 2 + j] * scale : -1e30f;
                    acc[mt][nt][half * 2 + j] = s;
                    m = fmaxf(m, s);
                }
            }
            m = fmaxf(m, __shfl_xor_sync(0xFFFFFFFFu, m, 1));
            m = fmaxf(m, __shfl_xor_sync(0xFFFFFFFFu, m, 2));
            if ((lane & 3) == 0) redmax[row][wn] = m;
        }
    }
    __syncthreads();
#pragma unroll
    for (int mt = 0; mt < 2; ++mt) {
#pragma unroll
        for (int half = 0; half < 2; ++half) {
            const int row = wm * 32 + mt * 16 + half * 8 + (lane >> 2);
            float m = fmaxf(fmaxf(redmax[row][0], redmax[row][1]),
                            fmaxf(redmax[row][2], redmax[row][3]));
            float sum = 0.0f;
#pragma unroll
            for (int nt = 0; nt < 6; ++nt) {
#pragma unroll
                for (int j = 0; j < 2; ++j) {
                    float s = acc[mt][nt][half * 2 + j];
                    float p = (s > -1e29f) ? __expf(s - m) : 0.0f;
                    acc[mt][nt][half * 2 + j] = p;
                    sum += p;
                }
            }
            sum += __shfl_xor_sync(0xFFFFFFFFu, sum, 1);
            sum += __shfl_xor_sync(0xFFFFFFFFu, sum, 2);
            if ((lane & 3) == 0) redsum[row][wn] = sum;
        }
    }
    __syncthreads();
    // Write P (fp16) to smem: 64 rows x 512B (192 cols used), swizzled
#pragma unroll
    for (int mt = 0; mt < 2; ++mt) {
#pragma unroll
        for (int half = 0; half < 2; ++half) {
            const int row = wm * 32 + mt * 16 + half * 8 + (lane >> 2);
            const float inv = 1.0f / (redsum[row][0] + redsum[row][1] +
                                      redsum[row][2] + redsum[row][3]);
#pragma unroll
            for (int nt = 0; nt < 6; ++nt) {
                const int col = wn * 48 + nt * 8 + (lane & 3) * 2;
                __half2 h;
                h.x = __float2half_rn(acc[mt][nt][half * 2 + 0] * inv);
                h.y = __float2half_rn(acc[mt][nt][half * 2 + 1] * inv);
                uint32_t off = (uint32_t)(row * 512 + col * 2);
                off ^= (off >> 5) & 0x70;
                asm volatile("st.shared.b32 [%0], %1;"
                             :: "r"(smem + P_OFF + off), "r"(*(uint32_t*)&h) : "memory");
            }
        }
    }
    __syncthreads();

    // ---------------- Phase 3: O = P @ V ----------------
    auto load_v = [&](int kc, int buf, int d0) {
        if (kb0 + kc * 32 + 31 < 0) return;    // fully padded chunk
        const uint32_t sb = smem + V_BASE + buf * 16384u;
#pragma unroll
        for (int i = 0; i < 4; ++i) {
            int idx = tid + i * 256;
            int r = idx >> 5, ch = idx & 31;
            int vrow = kb0 + kc * 32 + r; if (vrow < 0) vrow = 0;
            uint32_t dst = (uint32_t)(r * 512 + ((ch ^ (r & 7)) * 16));
            CP_ASYNC_16(sb + dst, a.v + ((size_t)b * TT + vrow) * DD + d0 + ch * 8);
        }
    };

    for (int dc = 0; dc < 4; ++dc) {
        const int d0 = dc * 256;
        float acc2[2][8][4];
#pragma unroll
        for (int mt = 0; mt < 2; ++mt)
#pragma unroll
            for (int nt = 0; nt < 8; ++nt)
#pragma unroll
                for (int j = 0; j < 4; ++j) acc2[mt][nt][j] = 0.0f;

        load_v(0, 0, d0);
        CP_ASYNC_COMMIT();
        for (int kc = 0; kc < 6; ++kc) {
            const int buf = kc & 1;
            if (kc + 1 < 6) {
                load_v(kc + 1, (kc + 1) & 1, d0);
                CP_ASYNC_COMMIT();
                CP_ASYNC_WAIT(1);
            } else {
                CP_ASYNC_WAIT(0);
            }
            __syncthreads();

            // Chunk unused by this warp's P rows?
            const bool pskip = ((kc * 32 + 31) <= (wm * 32)) ||
                               ((kc * 32) > (wm * 32 + 31 + SPAN)) ||
                               (kb0 + kc * 32 + 31 < 0);
            if (!pskip) {
                const uint32_t vb = smem + V_BASE + buf * 16384u;
#pragma unroll
                for (int ks = 0; ks < 2; ++ks) {
                    const int kbase = kc * 32 + ks * 16;
                    uint32_t pf[2][4];
#pragma unroll
                    for (int mt = 0; mt < 2; ++mt) {
                        const int prow = wm * 32 + mt * 16 + (lane & 15);
                        uint32_t aoff = (uint32_t)(prow * 512 + kbase * 2 + (lane >> 4) * 16);
                        aoff ^= (aoff >> 5) & 0x70;
                        LDMATRIX_X4(pf[mt][0], pf[mt][1], pf[mt][2], pf[mt][3],
                                    smem + P_OFF + aoff);
                    }
#pragma unroll
                    for (int ntp = 0; ntp < 4; ++ntp) {
                        const int vrow = ks * 16 + (lane & 15);
                        const int vcol = wn * 64 + ntp * 16 + ((lane >> 4) << 3);
                        uint32_t boff = (uint32_t)(vrow * 512 + vcol * 2);
                        boff ^= (boff >> 5) & 0x70;
                        uint32_t v0, v1, v2, v3;
                        LDMATRIX_X4T(v0, v1, v2, v3, vb + boff);
                        const int n0 = ntp * 2, n1 = ntp * 2 + 1;
#pragma unroll
                        for (int mt = 0; mt < 2; ++mt) {
                            MMA_F16(acc2[mt][n0][0], acc2[mt][n0][1], acc2[mt][n0][2], acc2[mt][n0][3],
                                    pf[mt][0], pf[mt][1], pf[mt][2], pf[mt][3], v0, v1);
                            MMA_F16(acc2[mt][n1][0], acc2[mt][n1][1], acc2[mt][n1][2], acc2[mt][n1][3],
                                    pf[mt][0], pf[mt][1], pf[mt][2], pf[mt][3], v2, v3);
                        }
                    }
                }
            }
            __syncthreads();
        }

        // Epilogue for this d-chunk
#pragma unroll
        for (int mt = 0; mt < 2; ++mt) {
#pragma unroll
            for (int nt = 0; nt < 8; ++nt) {
                const size_t row = qrow0 + wm * 32 + mt * 16 + (lane >> 2);
                const int col = d0 + wn * 64 + nt * 8 + (lane & 3) * 2;
                float2 v0 = make_float2(acc2[mt][nt][0], acc2[mt][nt][1]);
                float2 v1 = make_float2(acc2[mt][nt][2], acc2[mt][nt][3]);
                *reinterpret_cast<float2*>(a.out + row * DD + col) = v0;
                *reinterpret_cast<float2*>(a.out + (row + 8) * DD + col) = v1;
            }
        }
    }
}

// ---------------------------------------------------------------------------
extern "C" void kernel_launch(void* const* d_in, const int* in_sizes, int n_in,
                              void* d_out, int out_size) {
    const float* x  = (const float*)d_in[0];
    const float* Wq = (const float*)d_in[1];
    const float* bq = (const float*)d_in[2];
    const float* Wk = (const float*)d_in[3];
    const float* bk = (const float*)d_in[4];
    const float* Wv = (const float*)d_in[5];
    const float* bv = (const float*)d_in[6];
    float* out = (float*)d_out;

    __half *xh, *wh, *q, *k, *v;
    cudaGetSymbolAddress((void**)&xh, g_xh);
    cudaGetSymbolAddress((void**)&wh, g_wh);
    cudaGetSymbolAddress((void**)&q, g_q);
    cudaGetSymbolAddress((void**)&k, g_k);
    cudaGetSymbolAddress((void**)&v, g_v);

    // Convert fp32 -> fp16
    {
        int n4 = MROWS * DD / 4;
        cvt_f16<<<(n4 + 255) / 256, 256>>>(x, xh, n4);
        int w4x3 = 3 * DD * DD / 4;
        cvt_f16_w3<<<(w4x3 + 255) / 256, 256>>>(Wq, Wk, Wv, wh);
    }

    GemmArgs ga;
    ga.xh = xh;
    ga.wh[0] = wh;
    ga.wh[1] = wh + 1 * (size_t)DD * DD;
    ga.wh[2] = wh + 2 * (size_t)DD * DD;
    ga.bias[0] = bq; ga.bias[1] = bk; ga.bias[2] = bv;
    ga.out[0] = q; ga.out[1] = k; ga.out[2] = v;

    cudaFuncSetAttribute(qkv_tc_gemm, cudaFuncAttributeMaxDynamicSharedMemorySize,
                         GEMM_DSMEM);
    qkv_tc_gemm<<<dim3(DD / 128, MROWS / 128, 3), 256, GEMM_DSMEM>>>(ga);

    AttnArgs aa;
    aa.q = q; aa.k = k; aa.v = v;
    aa.out = out;
    cudaFuncSetAttribute(attn_tc, cudaFuncAttributeMaxDynamicSharedMemorySize,
                         ATTN_DSMEM);
    attn_tc<<<dim3(NB2, BB), 256, ATTN_DSMEM>>>(aa);
}